// round 9
// baseline (speedup 1.0000x reference)
#include <cuda_runtime.h>
#include <math.h>
#include <stdint.h>

// Problem constants
#define HD   4096
#define IS   2048
#define NE   16
#define NK   4
#define SIW  2048
#define TMAX 4096

// GEMM tile: CTA 128x128, 8 warps (2M x 4N), warp tile 64x32, K-chunk 32
#define BM   128
#define BN   128
#define BKT  32
#define LSTR 36                              // padded row stride (floats)
#define SM_A_FLOATS (BM * LSTR)              // 4608
#define SM_STAGE    (2 * SM_A_FLOATS)        // A + B per stage = 9216 floats
#define STAGE_BYTES (SM_STAGE * 4)           // 36864
#define DSMEM_BYTES (2 * STAGE_BYTES)        // 73728

// ---------------- static device scratch ----------------
__device__ int   d_cnt[NE];
__device__ int   d_tok[NE * TMAX];
__device__ float d_wgt[NE * TMAX];
__device__ float d_bufG[(size_t)NE * TMAX * IS];   // routed gate proj -> z (rounded)
__device__ float d_bufU[(size_t)NE * TMAX * IS];   // routed up proj
__device__ float d_sG[(size_t)TMAX * SIW];         // shared gate -> z (rounded)
__device__ float d_sU[(size_t)TMAX * SIW];         // shared up
__device__ float d_xr[(size_t)TMAX * HD];          // tf32-rounded x

__device__ __forceinline__ float* selw(int s) {
    switch (s) {
        case 0:  return d_bufG;
        case 1:  return d_bufU;
        case 2:  return d_sG;
        case 3:  return d_sU;
        default: return d_xr;
    }
}

// ---------------- helpers ----------------
__device__ __forceinline__ uint32_t smem_u32(const void* p) {
    uint32_t a;
    asm("{ .reg .u64 t; cvta.to.shared.u64 t, %1; cvt.u32.u64 %0, t; }" : "=r"(a) : "l"(p));
    return a;
}
__device__ __forceinline__ unsigned f2tf32(float f) {
    unsigned r;
    asm("cvt.rna.tf32.f32 %0, %1;" : "=r"(r) : "f"(f));
    return r;
}
__device__ __forceinline__ float rndf(float v) {
    return __uint_as_float(f2tf32(v));
}
#define CPA16(dst, src) \
    asm volatile("cp.async.cg.shared.global [%0], [%1], 16;" :: "r"(dst), "l"(src))
#define CPA_COMMIT() asm volatile("cp.async.commit_group;")
#define CPA_WAIT(n)  asm volatile("cp.async.wait_group %0;" :: "n"(n))

__device__ __forceinline__ void mma_tf32(float* d, const unsigned* a, unsigned b0, unsigned b1) {
    asm volatile(
        "mma.sync.aligned.m16n8k8.row.col.f32.tf32.tf32.f32 "
        "{%0,%1,%2,%3}, {%4,%5,%6,%7}, {%8,%9}, {%0,%1,%2,%3};"
        : "+f"(d[0]), "+f"(d[1]), "+f"(d[2]), "+f"(d[3])
        : "r"(a[0]), "r"(a[1]), "r"(a[2]), "r"(a[3]), "r"(b0), "r"(b1));
}

// ---------------- router ----------------
__global__ void zero_cnt_kernel() {
    if (threadIdx.x < NE) d_cnt[threadIdx.x] = 0;
}

__global__ void router_kernel(const float* __restrict__ x,
                              const float* __restrict__ gw,
                              const float* __restrict__ bias) {
    __shared__ float sx[HD];
    __shared__ float sc[NE];
    int t = blockIdx.x;
    const float4* xr = (const float4*)(x + (size_t)t * HD);
    for (int i = threadIdx.x; i < HD / 4; i += blockDim.x)
        ((float4*)sx)[i] = xr[i];
    __syncthreads();

    int warp = threadIdx.x >> 5, lane = threadIdx.x & 31;
    int nwarp = blockDim.x >> 5;
    for (int e = warp; e < NE; e += nwarp) {
        const float* w = gw + (size_t)e * HD;
        float s = 0.f;
        for (int i = lane; i < HD; i += 32) s = fmaf(sx[i], w[i], s);
        #pragma unroll
        for (int o = 16; o > 0; o >>= 1) s += __shfl_xor_sync(0xffffffffu, s, o);
        if (lane == 0) sc[e] = 1.f / (1.f + expf(-s)) + bias[e];
    }
    __syncthreads();

    if (threadIdx.x == 0) {
        float v[NE];
        #pragma unroll
        for (int e = 0; e < NE; e++) v[e] = sc[e];
        int idx[NK]; float wv[NK]; float sum = 0.f;
        #pragma unroll
        for (int k = 0; k < NK; k++) {
            int bi = 0; float bv = -1e30f;
            #pragma unroll
            for (int e = 0; e < NE; e++) if (v[e] > bv) { bv = v[e]; bi = e; }
            idx[k] = bi; wv[k] = bv; v[bi] = -1e30f; sum += bv;
        }
        float inv = 1.f / (sum + 1e-20f);
        #pragma unroll
        for (int k = 0; k < NK; k++) {
            int e = idx[k];
            int pos = atomicAdd(&d_cnt[e], 1);
            d_tok[e * TMAX + pos] = t;
            d_wgt[e * TMAX + pos] = wv[k] * inv;
        }
    }
}

// ---------------- tf32 pre-rounding (x only) ----------------
__global__ void round_kernel(const float4* __restrict__ in, int n4) {
    float4* out = (float4*)d_xr;
    int stride = gridDim.x * blockDim.x;
    for (int i = blockIdx.x * blockDim.x + threadIdx.x; i < n4; i += stride) {
        float4 v = in[i];
        float4 o;
        o.x = rndf(v.x); o.y = rndf(v.y); o.z = rndf(v.z); o.w = rndf(v.w);
        out[i] = o;
    }
}

// ---------------- tf32 mma.sync GEMM: C[M,N] = A[M,K] * B[N,K]^T ----------------
// 256 threads, 8 warps (2M x 4N), warp tile 64x32 -> acc 64 regs/thread,
// __launch_bounds__(256,2) targets 2 CTAs/SM for latency hiding.
// A: pre-rounded scratch (cp.async). B: raw fp32 weights, LDG -> cvt.rna -> STS.
// MODE 0: plain. MODE 1: gather A rows via token list, C = per-expert buffer.
// MODE 2: A = per-expert buffer, scatter-add C rows to out via token list.
template<int MODE>
__global__ __launch_bounds__(256, 2)
void gemm_mma(int aSel, const float* __restrict__ Bext, int cSel,
              float* __restrict__ Cext,
              int M, int K, int N, long long sB, long long sAC) {
    int e = blockIdx.z;
    const int* tok = d_tok + e * TMAX;
    if (MODE != 0) M = d_cnt[e];
    if ((int)blockIdx.y * BM >= M) return;

    const float* A = selw(aSel);
    const float* B = Bext + (size_t)e * sB;
    float* C = (cSel >= 0) ? selw(cSel) : Cext;
    if (MODE == 1) C += (size_t)e * sAC;
    if (MODE == 2) A += (size_t)e * sAC;

    extern __shared__ float smem[];
    uint32_t sbase = smem_u32(smem);

    int tid  = threadIdx.x;
    int lane = tid & 31;
    int warp = tid >> 5;
    int wm   = warp & 1;     // 2 warps along M (64 rows each)
    int wn   = warp >> 1;    // 4 warps along N (32 cols each)

    // ---- loader: thread owns (tid&7)*4 float offset, rows i*32 + (tid>>3) ----
    int lq = (tid & 7) * 4;
    int lr = tid >> 3;               // 0..31
    const float* aP[4];
    const float* bP[4];
    #pragma unroll
    for (int i = 0; i < 4; i++) {
        int r = blockIdx.y * BM + i * 32 + lr;
        int src;
        if (MODE == 1) src = (r < M) ? tok[r] : tok[0];
        else           src = (r < M) ? r : (M - 1);
        aP[i] = A + (size_t)src * K + lq;
        bP[i] = B + (size_t)(blockIdx.x * BN + i * 32 + lr) * K + lq;
    }
    uint32_t dOffA = (uint32_t)((lr * LSTR + lq) * 4);
    int      sOffB = SM_A_FLOATS + lr * LSTR + lq;

    float acc[4][4][4];
    #pragma unroll
    for (int i = 0; i < 4; i++)
        #pragma unroll
        for (int j = 0; j < 4; j++)
            #pragma unroll
            for (int q = 0; q < 4; q++) acc[i][j][q] = 0.f;

    int NT = K / BKT;
    float4 bReg[4];

    auto load_chunkA = [&](int c) {
        uint32_t sb = sbase + (uint32_t)(c & 1) * STAGE_BYTES;
        int k0 = c * BKT;
        #pragma unroll
        for (int i = 0; i < 4; i++)
            CPA16(sb + dOffA + (uint32_t)(i * 32 * LSTR * 4), aP[i] + k0);
        CPA_COMMIT();
    };
    auto ldg_B = [&](int c) {
        int k0 = c * BKT;
        #pragma unroll
        for (int i = 0; i < 4; i++)
            bReg[i] = *(const float4*)(bP[i] + k0);
    };
    auto sts_B = [&](int c) {
        float* st = smem + (c & 1) * SM_STAGE + sOffB;
        #pragma unroll
        for (int i = 0; i < 4; i++) {
            float4 v = bReg[i];
            float4 o;
            o.x = rndf(v.x); o.y = rndf(v.y); o.z = rndf(v.z); o.w = rndf(v.w);
            *(float4*)(st + i * 32 * LSTR) = o;
        }
    };

    // prologue: stage 0
    load_chunkA(0);
    ldg_B(0);
    sts_B(0);

    int aBase = (wm * 64 + (lane >> 2)) * LSTR + (lane & 3);
    int bBase = (wn * 32 + (lane >> 2)) * LSTR + (lane & 3);

    for (int s = 0; s < NT; s++) {
        CPA_WAIT(0);
        __syncthreads();      // stage s fully visible; all warps done with s-1

        if (s + 1 < NT) {
            ldg_B(s + 1);     // long-latency LDG issued before compute
            load_chunkA(s + 1);
        }

        const unsigned* as = (const unsigned*)(smem + (s & 1) * SM_STAGE);
        const unsigned* bs = as + SM_A_FLOATS;

        #pragma unroll
        for (int ks = 0; ks < BKT; ks += 8) {
            unsigned a[4][4];
            #pragma unroll
            for (int i = 0; i < 4; i++) {
                int base = aBase + i * 16 * LSTR + ks;
                a[i][0] = as[base];
                a[i][1] = as[base + 8 * LSTR];
                a[i][2] = as[base + 4];
                a[i][3] = as[base + 8 * LSTR + 4];
            }
            #pragma unroll
            for (int j = 0; j < 4; j++) {
                int bb = bBase + j * 8 * LSTR + ks;
                unsigned b0 = bs[bb];
                unsigned b1 = bs[bb + 4];
                #pragma unroll
                for (int i = 0; i < 4; i++)
                    mma_tf32(acc[i][j], a[i], b0, b1);
            }
        }

        if (s + 1 < NT) sts_B(s + 1);   // stage (s+1)&1: not read until after
                                        // next iteration's barrier
    }

    // ---- epilogue ----
    #pragma unroll
    for (int i = 0; i < 4; i++) {
        int r0 = blockIdx.y * BM + wm * 64 + i * 16 + (lane >> 2);
        #pragma unroll
        for (int j = 0; j < 4; j++) {
            int c0 = blockIdx.x * BN + wn * 32 + j * 8 + 2 * (lane & 3);
            if (MODE == 2) {
                if (r0 < M) {
                    int tr = tok[r0];
                    atomicAdd(C + (size_t)tr * N + c0,     acc[i][j][0]);
                    atomicAdd(C + (size_t)tr * N + c0 + 1, acc[i][j][1]);
                }
                if (r0 + 8 < M) {
                    int tr = tok[r0 + 8];
                    atomicAdd(C + (size_t)tr * N + c0,     acc[i][j][2]);
                    atomicAdd(C + (size_t)tr * N + c0 + 1, acc[i][j][3]);
                }
            } else {
                if (r0 < M) {
                    *(float2*)(C + (size_t)r0 * N + c0) =
                        make_float2(acc[i][j][0], acc[i][j][1]);
                }
                if (r0 + 8 < M) {
                    *(float2*)(C + (size_t)(r0 + 8) * N + c0) =
                        make_float2(acc[i][j][2], acc[i][j][3]);
                }
            }
        }
    }
}

// ---------------- activation kernels (store tf32-rounded z) ----------------
__device__ __forceinline__ float silu_f(float v) {
    return v / (1.f + expf(-v));
}

__global__ void routed_act_kernel() {
    int e = blockIdx.y;
    int row = blockIdx.x;
    if (row >= d_cnt[e]) return;
    float w = d_wgt[e * TMAX + row];
    size_t base = ((size_t)e * TMAX + row) * IS;
    float4* g4 = (float4*)(d_bufG + base);
    const float4* u4 = (const float4*)(d_bufU + base);
    for (int i = threadIdx.x; i < IS / 4; i += blockDim.x) {
        float4 g = g4[i], u = u4[i], z;
        z.x = rndf(silu_f(g.x) * u.x * w);
        z.y = rndf(silu_f(g.y) * u.y * w);
        z.z = rndf(silu_f(g.z) * u.z * w);
        z.w = rndf(silu_f(g.w) * u.w * w);
        g4[i] = z;
    }
}

__global__ void shared_act_kernel() {
    int row = blockIdx.x;
    size_t base = (size_t)row * SIW;
    float4* g4 = (float4*)(d_sG + base);
    const float4* u4 = (const float4*)(d_sU + base);
    for (int i = threadIdx.x; i < SIW / 4; i += blockDim.x) {
        float4 g = g4[i], u = u4[i], z;
        z.x = rndf(silu_f(g.x) * u.x);
        z.y = rndf(silu_f(g.y) * u.y);
        z.z = rndf(silu_f(g.z) * u.z);
        z.w = rndf(silu_f(g.w) * u.w);
        g4[i] = z;
    }
}

// ---------------- launch ----------------
extern "C" void kernel_launch(void* const* d_in, const int* in_sizes, int n_in,
                              void* d_out, int out_size) {
    const float* x    = (const float*)d_in[0];
    const float* gw   = (const float*)d_in[1];
    const float* bias = (const float*)d_in[2];
    const float* Wg   = (const float*)d_in[3];
    const float* Wu   = (const float*)d_in[4];
    const float* Wd   = (const float*)d_in[5];
    const float* Sg   = (const float*)d_in[6];
    const float* Su   = (const float*)d_in[7];
    const float* Sd   = (const float*)d_in[8];
    float* out = (float*)d_out;

    int Tn = in_sizes[0] / HD;            // 4096 tokens
    int mt = (Tn + BM - 1) / BM;          // 32

    static int smem_set = 0;
    if (!smem_set) {
        cudaFuncSetAttribute(gemm_mma<0>, cudaFuncAttributeMaxDynamicSharedMemorySize, DSMEM_BYTES);
        cudaFuncSetAttribute(gemm_mma<1>, cudaFuncAttributeMaxDynamicSharedMemorySize, DSMEM_BYTES);
        cudaFuncSetAttribute(gemm_mma<2>, cudaFuncAttributeMaxDynamicSharedMemorySize, DSMEM_BYTES);
        smem_set = 1;
    }

    zero_cnt_kernel<<<1, 32>>>();
    router_kernel<<<Tn, 128>>>(x, gw, bias);

    // tf32 pre-rounding of x only (weights rounded in-register inside GEMMs)
    round_kernel<<<2048, 256>>>((const float4*)x, (int)((size_t)Tn * HD / 4));

    // shared expert
    gemm_mma<0><<<dim3(SIW / BN, mt, 1), 256, DSMEM_BYTES>>>(4, Sg, 2, nullptr, Tn, HD, SIW, 0, 0);
    gemm_mma<0><<<dim3(SIW / BN, mt, 1), 256, DSMEM_BYTES>>>(4, Su, 3, nullptr, Tn, HD, SIW, 0, 0);
    shared_act_kernel<<<Tn, 256>>>();
    gemm_mma<0><<<dim3(HD / BN, mt, 1), 256, DSMEM_BYTES>>>(2, Sd, -1, out, Tn, SIW, HD, 0, 0);

    // routed experts (sparse)
    gemm_mma<1><<<dim3(IS / BN, TMAX / BM, NE), 256, DSMEM_BYTES>>>(
        4, Wg, 0, nullptr, 0, HD, IS, (long long)IS * HD, (long long)TMAX * IS);
    gemm_mma<1><<<dim3(IS / BN, TMAX / BM, NE), 256, DSMEM_BYTES>>>(
        4, Wu, 1, nullptr, 0, HD, IS, (long long)IS * HD, (long long)TMAX * IS);
    routed_act_kernel<<<dim3(Tn, NE), 256>>>();
    gemm_mma<2><<<dim3(HD / BN, TMAX / BM, NE), 256, DSMEM_BYTES>>>(
        0, Wd, -1, out, 0, IS, HD, (long long)HD * IS, (long long)TMAX * IS);

    (void)n_in; (void)out_size;
}

// round 11
// speedup vs baseline: 1.0791x; 1.0791x over previous
#include <cuda_runtime.h>
#include <math.h>
#include <stdint.h>

// Problem constants
#define HD   4096
#define IS   2048
#define NE   16
#define NK   4
#define SIW  2048
#define TMAX 4096

// GEMM tile: CTA 128x128, 8 warps (2M x 4N), warp tile 64x32, K-chunk 32
#define BM   128
#define BN   128
#define BKT  32
#define LSTR 36                              // padded row stride (floats)
#define SM_A_FLOATS (BM * LSTR)              // 4608
#define SM_STAGE    (2 * SM_A_FLOATS)        // A + B per stage = 9216 floats
#define STAGE_BYTES (SM_STAGE * 4)           // 36864
#define DSMEM_BYTES (2 * STAGE_BYTES)        // 73728

// ---------------- static device scratch ----------------
__device__ int   d_cnt[NE];
__device__ int   d_tok[NE * TMAX];
__device__ float d_wgt[NE * TMAX];
__device__ float d_bufG[(size_t)NE * TMAX * IS];   // routed gate proj -> z (rounded)
__device__ float d_bufU[(size_t)NE * TMAX * IS];   // routed up proj
__device__ float d_sG[(size_t)TMAX * SIW];         // shared gate -> z (rounded)
__device__ float d_sU[(size_t)TMAX * SIW];         // shared up
__device__ float d_xr[(size_t)TMAX * HD];          // tf32-rounded x

__device__ __forceinline__ float* selw(int s) {
    switch (s) {
        case 0:  return d_bufG;
        case 1:  return d_bufU;
        case 2:  return d_sG;
        case 3:  return d_sU;
        default: return d_xr;
    }
}

// ---------------- helpers ----------------
__device__ __forceinline__ uint32_t smem_u32(const void* p) {
    uint32_t a;
    asm("{ .reg .u64 t; cvta.to.shared.u64 t, %1; cvt.u32.u64 %0, t; }" : "=r"(a) : "l"(p));
    return a;
}
__device__ __forceinline__ unsigned f2tf32(float f) {
    unsigned r;
    asm("cvt.rna.tf32.f32 %0, %1;" : "=r"(r) : "f"(f));
    return r;
}
__device__ __forceinline__ float rndf(float v) {
    return __uint_as_float(f2tf32(v));
}
#define CPA16(dst, src) \
    asm volatile("cp.async.cg.shared.global [%0], [%1], 16;" :: "r"(dst), "l"(src))
#define CPA_COMMIT() asm volatile("cp.async.commit_group;")
#define CPA_WAIT(n)  asm volatile("cp.async.wait_group %0;" :: "n"(n))

#define LDSM4(r0, r1, r2, r3, addr) \
    asm volatile("ldmatrix.sync.aligned.m8n8.x4.shared.b16 {%0,%1,%2,%3}, [%4];" \
                 : "=r"(r0), "=r"(r1), "=r"(r2), "=r"(r3) : "r"(addr))

__device__ __forceinline__ void mma_tf32(float* d, const unsigned* a, unsigned b0, unsigned b1) {
    asm volatile(
        "mma.sync.aligned.m16n8k8.row.col.f32.tf32.tf32.f32 "
        "{%0,%1,%2,%3}, {%4,%5,%6,%7}, {%8,%9}, {%0,%1,%2,%3};"
        : "+f"(d[0]), "+f"(d[1]), "+f"(d[2]), "+f"(d[3])
        : "r"(a[0]), "r"(a[1]), "r"(a[2]), "r"(a[3]), "r"(b0), "r"(b1));
}

// ---------------- router ----------------
__global__ void zero_cnt_kernel() {
    if (threadIdx.x < NE) d_cnt[threadIdx.x] = 0;
}

__global__ void router_kernel(const float* __restrict__ x,
                              const float* __restrict__ gw,
                              const float* __restrict__ bias) {
    __shared__ float sx[HD];
    __shared__ float sc[NE];
    int t = blockIdx.x;
    const float4* xr = (const float4*)(x + (size_t)t * HD);
    for (int i = threadIdx.x; i < HD / 4; i += blockDim.x)
        ((float4*)sx)[i] = xr[i];
    __syncthreads();

    int warp = threadIdx.x >> 5, lane = threadIdx.x & 31;
    int nwarp = blockDim.x >> 5;
    for (int e = warp; e < NE; e += nwarp) {
        const float* w = gw + (size_t)e * HD;
        float s = 0.f;
        for (int i = lane; i < HD; i += 32) s = fmaf(sx[i], w[i], s);
        #pragma unroll
        for (int o = 16; o > 0; o >>= 1) s += __shfl_xor_sync(0xffffffffu, s, o);
        if (lane == 0) sc[e] = 1.f / (1.f + expf(-s)) + bias[e];
    }
    __syncthreads();

    if (threadIdx.x == 0) {
        float v[NE];
        #pragma unroll
        for (int e = 0; e < NE; e++) v[e] = sc[e];
        int idx[NK]; float wv[NK]; float sum = 0.f;
        #pragma unroll
        for (int k = 0; k < NK; k++) {
            int bi = 0; float bv = -1e30f;
            #pragma unroll
            for (int e = 0; e < NE; e++) if (v[e] > bv) { bv = v[e]; bi = e; }
            idx[k] = bi; wv[k] = bv; v[bi] = -1e30f; sum += bv;
        }
        float inv = 1.f / (sum + 1e-20f);
        #pragma unroll
        for (int k = 0; k < NK; k++) {
            int e = idx[k];
            int pos = atomicAdd(&d_cnt[e], 1);
            d_tok[e * TMAX + pos] = t;
            d_wgt[e * TMAX + pos] = wv[k] * inv;
        }
    }
}

// ---------------- tf32 pre-rounding (x only) ----------------
__global__ void round_kernel(const float4* __restrict__ in, int n4) {
    float4* out = (float4*)d_xr;
    int stride = gridDim.x * blockDim.x;
    for (int i = blockIdx.x * blockDim.x + threadIdx.x; i < n4; i += stride) {
        float4 v = in[i];
        float4 o;
        o.x = rndf(v.x); o.y = rndf(v.y); o.z = rndf(v.z); o.w = rndf(v.w);
        out[i] = o;
    }
}

// ---------------- tf32 mma.sync GEMM: C[M,N] = A[M,K] * B[N,K]^T ----------------
// 256 threads, 8 warps (2M x 4N), warp tile 64x32. Fragments loaded via
// ldmatrix.x4 (6 LDSM per k8-step instead of 24 scalar LDS -> LSU unbound).
// A: pre-rounded scratch (cp.async). B: raw fp32 weights, LDG -> cvt.rna -> STS.
// MODE 0: plain. MODE 1: gather A rows via token list, C = per-expert buffer.
// MODE 2: A = per-expert buffer, scatter-add C rows to out via token list.
template<int MODE>
__global__ __launch_bounds__(256, 2)
void gemm_mma(int aSel, const float* __restrict__ Bext, int cSel,
              float* __restrict__ Cext,
              int M, int K, int N, long long sB, long long sAC) {
    int e = blockIdx.z;
    const int* tok = d_tok + e * TMAX;
    if (MODE != 0) M = d_cnt[e];
    if ((int)blockIdx.y * BM >= M) return;

    const float* A = selw(aSel);
    const float* B = Bext + (size_t)e * sB;
    float* C = (cSel >= 0) ? selw(cSel) : Cext;
    if (MODE == 1) C += (size_t)e * sAC;
    if (MODE == 2) A += (size_t)e * sAC;

    extern __shared__ float smem[];
    uint32_t sbase = smem_u32(smem);

    int tid  = threadIdx.x;
    int lane = tid & 31;
    int warp = tid >> 5;
    int wm   = warp & 1;     // 2 warps along M (64 rows each)
    int wn   = warp >> 1;    // 4 warps along N (32 cols each)

    // ---- loader: thread owns (tid&7)*4 float offset, rows i*32 + (tid>>3) ----
    int lq = (tid & 7) * 4;
    int lr = tid >> 3;               // 0..31
    const float* aP[4];
    const float* bP[4];
    #pragma unroll
    for (int i = 0; i < 4; i++) {
        int r = blockIdx.y * BM + i * 32 + lr;
        int src;
        if (MODE == 1) src = (r < M) ? tok[r] : tok[0];
        else           src = (r < M) ? r : (M - 1);
        aP[i] = A + (size_t)src * K + lq;
        bP[i] = B + (size_t)(blockIdx.x * BN + i * 32 + lr) * K + lq;
    }
    uint32_t dOffA = (uint32_t)((lr * LSTR + lq) * 4);
    int      sOffB = SM_A_FLOATS + lr * LSTR + lq;

    // ---- ldmatrix lane addresses (stage-0 base, bytes) ----
    // A subtile i (16x8): lanes 0-15 rows, col group (lane>>4)*4
    uint32_t aAddr[4];
    #pragma unroll
    for (int i = 0; i < 4; i++) {
        int row = wm * 64 + i * 16 + (lane & 15);
        int col = (lane >> 4) << 2;
        aAddr[i] = sbase + (uint32_t)((row * LSTR + col) << 2);
    }
    // B j-pair p (16 n-rows x 8 k): lanes select n row + k half
    uint32_t bAddr[2];
    #pragma unroll
    for (int p = 0; p < 2; p++) {
        int nrow = wn * 32 + p * 16 + ((lane >> 4) << 3) + (lane & 7);
        int col  = ((lane >> 3) & 1) << 2;
        bAddr[p] = sbase + (uint32_t)(SM_A_FLOATS * 4) +
                   (uint32_t)((nrow * LSTR + col) << 2);
    }

    float acc[4][4][4];
    #pragma unroll
    for (int i = 0; i < 4; i++)
        #pragma unroll
        for (int j = 0; j < 4; j++)
            #pragma unroll
            for (int q = 0; q < 4; q++) acc[i][j][q] = 0.f;

    int NT = K / BKT;
    float4 bReg[4];

    auto load_chunkA = [&](int c) {
        uint32_t sb = sbase + (uint32_t)(c & 1) * STAGE_BYTES;
        int k0 = c * BKT;
        #pragma unroll
        for (int i = 0; i < 4; i++)
            CPA16(sb + dOffA + (uint32_t)(i * 32 * LSTR * 4), aP[i] + k0);
        CPA_COMMIT();
    };
    auto ldg_B = [&](int c) {
        int k0 = c * BKT;
        #pragma unroll
        for (int i = 0; i < 4; i++)
            bReg[i] = *(const float4*)(bP[i] + k0);
    };
    auto sts_B = [&](int c) {
        float* st = smem + (c & 1) * SM_STAGE + sOffB;
        #pragma unroll
        for (int i = 0; i < 4; i++) {
            float4 v = bReg[i];
            float4 o;
            o.x = rndf(v.x); o.y = rndf(v.y); o.z = rndf(v.z); o.w = rndf(v.w);
            *(float4*)(st + i * 32 * LSTR) = o;
        }
    };

    // prologue: stage 0
    load_chunkA(0);
    ldg_B(0);
    sts_B(0);

    for (int s = 0; s < NT; s++) {
        CPA_WAIT(0);
        __syncthreads();      // stage s fully visible; all warps done with s-1

        if (s + 1 < NT) {
            ldg_B(s + 1);     // long-latency LDG issued before compute
            load_chunkA(s + 1);
        }

        uint32_t stOff = (uint32_t)(s & 1) * STAGE_BYTES;

        #pragma unroll
        for (int ks = 0; ks < BKT; ks += 8) {
            uint32_t kOff = stOff + (uint32_t)(ks << 2);
            unsigned a[4][4];
            #pragma unroll
            for (int i = 0; i < 4; i++)
                LDSM4(a[i][0], a[i][1], a[i][2], a[i][3], aAddr[i] + kOff);
            unsigned b[2][4];
            #pragma unroll
            for (int p = 0; p < 2; p++)
                LDSM4(b[p][0], b[p][1], b[p][2], b[p][3], bAddr[p] + kOff);
            #pragma unroll
            for (int j = 0; j < 4; j++) {
                unsigned b0 = b[j >> 1][(j & 1) * 2];
                unsigned b1 = b[j >> 1][(j & 1) * 2 + 1];
                #pragma unroll
                for (int i = 0; i < 4; i++)
                    mma_tf32(acc[i][j], a[i], b0, b1);
            }
        }

        if (s + 1 < NT) sts_B(s + 1);   // stage (s+1)&1: not read until after
                                        // next iteration's barrier
    }

    // ---- epilogue ----
    #pragma unroll
    for (int i = 0; i < 4; i++) {
        int r0 = blockIdx.y * BM + wm * 64 + i * 16 + (lane >> 2);
        #pragma unroll
        for (int j = 0; j < 4; j++) {
            int c0 = blockIdx.x * BN + wn * 32 + j * 8 + 2 * (lane & 3);
            if (MODE == 2) {
                if (r0 < M) {
                    int tr = tok[r0];
                    atomicAdd(C + (size_t)tr * N + c0,     acc[i][j][0]);
                    atomicAdd(C + (size_t)tr * N + c0 + 1, acc[i][j][1]);
                }
                if (r0 + 8 < M) {
                    int tr = tok[r0 + 8];
                    atomicAdd(C + (size_t)tr * N + c0,     acc[i][j][2]);
                    atomicAdd(C + (size_t)tr * N + c0 + 1, acc[i][j][3]);
                }
            } else {
                if (r0 < M) {
                    *(float2*)(C + (size_t)r0 * N + c0) =
                        make_float2(acc[i][j][0], acc[i][j][1]);
                }
                if (r0 + 8 < M) {
                    *(float2*)(C + (size_t)(r0 + 8) * N + c0) =
                        make_float2(acc[i][j][2], acc[i][j][3]);
                }
            }
        }
    }
}

// ---------------- activation kernels (store tf32-rounded z) ----------------
__device__ __forceinline__ float silu_f(float v) {
    return v / (1.f + expf(-v));
}

__global__ void routed_act_kernel() {
    int e = blockIdx.y;
    int row = blockIdx.x;
    if (row >= d_cnt[e]) return;
    float w = d_wgt[e * TMAX + row];
    size_t base = ((size_t)e * TMAX + row) * IS;
    float4* g4 = (float4*)(d_bufG + base);
    const float4* u4 = (const float4*)(d_bufU + base);
    for (int i = threadIdx.x; i < IS / 4; i += blockDim.x) {
        float4 g = g4[i], u = u4[i], z;
        z.x = rndf(silu_f(g.x) * u.x * w);
        z.y = rndf(silu_f(g.y) * u.y * w);
        z.z = rndf(silu_f(g.z) * u.z * w);
        z.w = rndf(silu_f(g.w) * u.w * w);
        g4[i] = z;
    }
}

__global__ void shared_act_kernel() {
    int row = blockIdx.x;
    size_t base = (size_t)row * SIW;
    float4* g4 = (float4*)(d_sG + base);
    const float4* u4 = (const float4*)(d_sU + base);
    for (int i = threadIdx.x; i < SIW / 4; i += blockDim.x) {
        float4 g = g4[i], u = u4[i], z;
        z.x = rndf(silu_f(g.x) * u.x);
        z.y = rndf(silu_f(g.y) * u.y);
        z.z = rndf(silu_f(g.z) * u.z);
        z.w = rndf(silu_f(g.w) * u.w);
        g4[i] = z;
    }
}

// ---------------- launch ----------------
extern "C" void kernel_launch(void* const* d_in, const int* in_sizes, int n_in,
                              void* d_out, int out_size) {
    const float* x    = (const float*)d_in[0];
    const float* gw   = (const float*)d_in[1];
    const float* bias = (const float*)d_in[2];
    const float* Wg   = (const float*)d_in[3];
    const float* Wu   = (const float*)d_in[4];
    const float* Wd   = (const float*)d_in[5];
    const float* Sg   = (const float*)d_in[6];
    const float* Su   = (const float*)d_in[7];
    const float* Sd   = (const float*)d_in[8];
    float* out = (float*)d_out;

    int Tn = in_sizes[0] / HD;            // 4096 tokens
    int mt = (Tn + BM - 1) / BM;          // 32

    static int smem_set = 0;
    if (!smem_set) {
        cudaFuncSetAttribute(gemm_mma<0>, cudaFuncAttributeMaxDynamicSharedMemorySize, DSMEM_BYTES);
        cudaFuncSetAttribute(gemm_mma<1>, cudaFuncAttributeMaxDynamicSharedMemorySize, DSMEM_BYTES);
        cudaFuncSetAttribute(gemm_mma<2>, cudaFuncAttributeMaxDynamicSharedMemorySize, DSMEM_BYTES);
        smem_set = 1;
    }

    zero_cnt_kernel<<<1, 32>>>();
    router_kernel<<<Tn, 128>>>(x, gw, bias);

    // tf32 pre-rounding of x only (weights rounded in-register inside GEMMs)
    round_kernel<<<2048, 256>>>((const float4*)x, (int)((size_t)Tn * HD / 4));

    // shared expert
    gemm_mma<0><<<dim3(SIW / BN, mt, 1), 256, DSMEM_BYTES>>>(4, Sg, 2, nullptr, Tn, HD, SIW, 0, 0);
    gemm_mma<0><<<dim3(SIW / BN, mt, 1), 256, DSMEM_BYTES>>>(4, Su, 3, nullptr, Tn, HD, SIW, 0, 0);
    shared_act_kernel<<<Tn, 256>>>();
    gemm_mma<0><<<dim3(HD / BN, mt, 1), 256, DSMEM_BYTES>>>(2, Sd, -1, out, Tn, SIW, HD, 0, 0);

    // routed experts (sparse)
    gemm_mma<1><<<dim3(IS / BN, TMAX / BM, NE), 256, DSMEM_BYTES>>>(
        4, Wg, 0, nullptr, 0, HD, IS, (long long)IS * HD, (long long)TMAX * IS);
    gemm_mma<1><<<dim3(IS / BN, TMAX / BM, NE), 256, DSMEM_BYTES>>>(
        4, Wu, 1, nullptr, 0, HD, IS, (long long)IS * HD, (long long)TMAX * IS);
    routed_act_kernel<<<dim3(Tn, NE), 256>>>();
    gemm_mma<2><<<dim3(HD / BN, TMAX / BM, NE), 256, DSMEM_BYTES>>>(
        0, Wd, -1, out, 0, IS, HD, (long long)HD * IS, (long long)TMAX * IS);

    (void)n_in; (void)out_size;
}

// round 12
// speedup vs baseline: 1.1465x; 1.0624x over previous
#include <cuda_runtime.h>
#include <math.h>
#include <stdint.h>

// Problem constants
#define HD   4096
#define IS   2048
#define NE   16
#define NK   4
#define SIW  2048
#define TMAX 4096

// GEMM tile: CTA 128x128, 8 warps (2M x 4N), warp tile 64x32, K-chunk 32
#define BM   128
#define BN   128
#define BKT  32
#define LSTR 36                              // padded row stride (floats)
#define SM_A_FLOATS (BM * LSTR)              // 4608
#define SM_STAGE    (2 * SM_A_FLOATS)        // A + B per stage = 9216 floats
#define STAGE_BYTES (SM_STAGE * 4)           // 36864
#define DSMEM_BYTES (2 * STAGE_BYTES)        // 73728

// ---------------- static device scratch ----------------
__device__ int   d_cnt[NE];
__device__ int   d_tok[NE * TMAX];
__device__ float d_wgt[NE * TMAX];
__device__ float d_bufG[(size_t)NE * TMAX * IS];   // routed gate proj -> z (rounded)
__device__ float d_bufU[(size_t)NE * TMAX * IS];   // routed up proj
__device__ float d_sG[(size_t)TMAX * SIW];         // shared gate -> z (rounded)
__device__ float d_sU[(size_t)TMAX * SIW];         // shared up
__device__ float d_xr[(size_t)TMAX * HD];          // tf32-rounded x

// ---------------- helpers ----------------
__device__ __forceinline__ uint32_t smem_u32(const void* p) {
    uint32_t a;
    asm("{ .reg .u64 t; cvta.to.shared.u64 t, %1; cvt.u32.u64 %0, t; }" : "=r"(a) : "l"(p));
    return a;
}
__device__ __forceinline__ unsigned f2tf32(float f) {
    unsigned r;
    asm("cvt.rna.tf32.f32 %0, %1;" : "=r"(r) : "f"(f));
    return r;
}
__device__ __forceinline__ float rndf(float v) {
    return __uint_as_float(f2tf32(v));
}
#define CPA16(dst, src) \
    asm volatile("cp.async.cg.shared.global [%0], [%1], 16;" :: "r"(dst), "l"(src))
#define CPA_COMMIT() asm volatile("cp.async.commit_group;")
#define CPA_WAIT(n)  asm volatile("cp.async.wait_group %0;" :: "n"(n))

#define LDSM4(r0, r1, r2, r3, addr) \
    asm volatile("ldmatrix.sync.aligned.m8n8.x4.shared.b16 {%0,%1,%2,%3}, [%4];" \
                 : "=r"(r0), "=r"(r1), "=r"(r2), "=r"(r3) : "r"(addr))

__device__ __forceinline__ void mma_tf32(float* d, const unsigned* a, unsigned b0, unsigned b1) {
    asm volatile(
        "mma.sync.aligned.m16n8k8.row.col.f32.tf32.tf32.f32 "
        "{%0,%1,%2,%3}, {%4,%5,%6,%7}, {%8,%9}, {%0,%1,%2,%3};"
        : "+f"(d[0]), "+f"(d[1]), "+f"(d[2]), "+f"(d[3])
        : "r"(a[0]), "r"(a[1]), "r"(a[2]), "r"(a[3]), "r"(b0), "r"(b1));
}

// ---------------- router ----------------
__global__ void zero_cnt_kernel() {
    if (threadIdx.x < NE) d_cnt[threadIdx.x] = 0;
}

__global__ void router_kernel(const float* __restrict__ x,
                              const float* __restrict__ gw,
                              const float* __restrict__ bias) {
    __shared__ float sx[HD];
    __shared__ float sc[NE];
    int t = blockIdx.x;
    const float4* xr = (const float4*)(x + (size_t)t * HD);
    for (int i = threadIdx.x; i < HD / 4; i += blockDim.x)
        ((float4*)sx)[i] = xr[i];
    __syncthreads();

    int warp = threadIdx.x >> 5, lane = threadIdx.x & 31;
    int nwarp = blockDim.x >> 5;
    for (int e = warp; e < NE; e += nwarp) {
        const float* w = gw + (size_t)e * HD;
        float s = 0.f;
        for (int i = lane; i < HD; i += 32) s = fmaf(sx[i], w[i], s);
        #pragma unroll
        for (int o = 16; o > 0; o >>= 1) s += __shfl_xor_sync(0xffffffffu, s, o);
        if (lane == 0) sc[e] = 1.f / (1.f + expf(-s)) + bias[e];
    }
    __syncthreads();

    if (threadIdx.x == 0) {
        float v[NE];
        #pragma unroll
        for (int e = 0; e < NE; e++) v[e] = sc[e];
        int idx[NK]; float wv[NK]; float sum = 0.f;
        #pragma unroll
        for (int k = 0; k < NK; k++) {
            int bi = 0; float bv = -1e30f;
            #pragma unroll
            for (int e = 0; e < NE; e++) if (v[e] > bv) { bv = v[e]; bi = e; }
            idx[k] = bi; wv[k] = bv; v[bi] = -1e30f; sum += bv;
        }
        float inv = 1.f / (sum + 1e-20f);
        #pragma unroll
        for (int k = 0; k < NK; k++) {
            int e = idx[k];
            int pos = atomicAdd(&d_cnt[e], 1);
            d_tok[e * TMAX + pos] = t;
            d_wgt[e * TMAX + pos] = wv[k] * inv;
        }
    }
}

// ---------------- tf32 pre-rounding (x only) ----------------
__global__ void round_kernel(const float4* __restrict__ in, int n4) {
    float4* out = (float4*)d_xr;
    int stride = gridDim.x * blockDim.x;
    for (int i = blockIdx.x * blockDim.x + threadIdx.x; i < n4; i += stride) {
        float4 v = in[i];
        float4 o;
        o.x = rndf(v.x); o.y = rndf(v.y); o.z = rndf(v.z); o.w = rndf(v.w);
        out[i] = o;
    }
}

// ============ shared GEMM core (device inline) ============
// C[M,N] = A[M,K] * B[N,K]^T ; A rows indirected via rowIdx semantics.
// GATHER: A row r comes from tok list. C written directly (float2 stores) if
// ATOMIC==0, else atomicAdd scattered via tok.
template<int GATHER, int ATOMIC>
__device__ __forceinline__ void gemm_core(
    const float* __restrict__ A, const float* __restrict__ B,
    float* __restrict__ C, const int* __restrict__ tok,
    int M, int K, int N, int by, int bx)
{
    extern __shared__ float smem[];
    uint32_t sbase = smem_u32(smem);

    int tid  = threadIdx.x;
    int lane = tid & 31;
    int warp = tid >> 5;
    int wm   = warp & 1;
    int wn   = warp >> 1;

    int lq = (tid & 7) * 4;
    int lr = tid >> 3;
    const float* aP[4];
    const float* bP[4];
    #pragma unroll
    for (int i = 0; i < 4; i++) {
        int r = by * BM + i * 32 + lr;
        int src;
        if (GATHER) src = (r < M) ? tok[r] : tok[0];
        else        src = (r < M) ? r : (M - 1);
        aP[i] = A + (size_t)src * K + lq;
        bP[i] = B + (size_t)(bx * BN + i * 32 + lr) * K + lq;
    }
    uint32_t dOffA = (uint32_t)((lr * LSTR + lq) * 4);
    int      sOffB = SM_A_FLOATS + lr * LSTR + lq;

    uint32_t aAddr[4];
    #pragma unroll
    for (int i = 0; i < 4; i++) {
        int row = wm * 64 + i * 16 + (lane & 15);
        int col = (lane >> 4) << 2;
        aAddr[i] = sbase + (uint32_t)((row * LSTR + col) << 2);
    }
    uint32_t bAddr[2];
    #pragma unroll
    for (int p = 0; p < 2; p++) {
        int nrow = wn * 32 + p * 16 + ((lane >> 4) << 3) + (lane & 7);
        int col  = ((lane >> 3) & 1) << 2;
        bAddr[p] = sbase + (uint32_t)(SM_A_FLOATS * 4) +
                   (uint32_t)((nrow * LSTR + col) << 2);
    }

    float acc[4][4][4];
    #pragma unroll
    for (int i = 0; i < 4; i++)
        #pragma unroll
        for (int j = 0; j < 4; j++)
            #pragma unroll
            for (int q = 0; q < 4; q++) acc[i][j][q] = 0.f;

    int NT = K / BKT;
    float4 bReg[4];

    auto load_chunkA = [&](int c) {
        uint32_t sb = sbase + (uint32_t)(c & 1) * STAGE_BYTES;
        int k0 = c * BKT;
        #pragma unroll
        for (int i = 0; i < 4; i++)
            CPA16(sb + dOffA + (uint32_t)(i * 32 * LSTR * 4), aP[i] + k0);
        CPA_COMMIT();
    };
    auto ldg_B = [&](int c) {
        int k0 = c * BKT;
        #pragma unroll
        for (int i = 0; i < 4; i++)
            bReg[i] = *(const float4*)(bP[i] + k0);
    };
    auto sts_B = [&](int c) {
        float* st = smem + (c & 1) * SM_STAGE + sOffB;
        #pragma unroll
        for (int i = 0; i < 4; i++) {
            float4 v = bReg[i];
            float4 o;
            o.x = rndf(v.x); o.y = rndf(v.y); o.z = rndf(v.z); o.w = rndf(v.w);
            *(float4*)(st + i * 32 * LSTR) = o;
        }
    };

    load_chunkA(0);
    ldg_B(0);
    sts_B(0);

    for (int s = 0; s < NT; s++) {
        CPA_WAIT(0);
        __syncthreads();

        if (s + 1 < NT) {
            ldg_B(s + 1);
            load_chunkA(s + 1);
        }

        uint32_t stOff = (uint32_t)(s & 1) * STAGE_BYTES;

        #pragma unroll
        for (int ks = 0; ks < BKT; ks += 8) {
            uint32_t kOff = stOff + (uint32_t)(ks << 2);
            unsigned a[4][4];
            #pragma unroll
            for (int i = 0; i < 4; i++)
                LDSM4(a[i][0], a[i][1], a[i][2], a[i][3], aAddr[i] + kOff);
            unsigned b[2][4];
            #pragma unroll
            for (int p = 0; p < 2; p++)
                LDSM4(b[p][0], b[p][1], b[p][2], b[p][3], bAddr[p] + kOff);
            #pragma unroll
            for (int j = 0; j < 4; j++) {
                unsigned b0 = b[j >> 1][(j & 1) * 2];
                unsigned b1 = b[j >> 1][(j & 1) * 2 + 1];
                #pragma unroll
                for (int i = 0; i < 4; i++)
                    mma_tf32(acc[i][j], a[i], b0, b1);
            }
        }

        if (s + 1 < NT) sts_B(s + 1);
    }

    // epilogue
    #pragma unroll
    for (int i = 0; i < 4; i++) {
        int r0 = by * BM + wm * 64 + i * 16 + (lane >> 2);
        #pragma unroll
        for (int j = 0; j < 4; j++) {
            int c0 = bx * BN + wn * 32 + j * 8 + 2 * (lane & 3);
            if (ATOMIC) {
                if (r0 < M) {
                    int tr = tok[r0];
                    atomicAdd(C + (size_t)tr * N + c0,     acc[i][j][0]);
                    atomicAdd(C + (size_t)tr * N + c0 + 1, acc[i][j][1]);
                }
                if (r0 + 8 < M) {
                    int tr = tok[r0 + 8];
                    atomicAdd(C + (size_t)tr * N + c0,     acc[i][j][2]);
                    atomicAdd(C + (size_t)tr * N + c0 + 1, acc[i][j][3]);
                }
            } else {
                if (r0 < M) {
                    *(float2*)(C + (size_t)r0 * N + c0) =
                        make_float2(acc[i][j][0], acc[i][j][1]);
                }
                if (r0 + 8 < M) {
                    *(float2*)(C + (size_t)(r0 + 8) * N + c0) =
                        make_float2(acc[i][j][2], acc[i][j][3]);
                }
            }
        }
    }
}

// ---------------- fused gate+up GEMM launch ----------------
// grid (32, 32, NE+1):
//   blockIdx.x: [0,16) gate half, [16,32) up half; bx = x & 15
//   z in [0,NE): routed expert z (gather A rows, C = per-expert buffer)
//   z == NE   : shared expert (plain A, C = d_sG / d_sU)
__global__ __launch_bounds__(256, 2)
void gemm_gu(const float* __restrict__ Wg, const float* __restrict__ Wu,
             const float* __restrict__ Sg, const float* __restrict__ Su,
             int Tn) {
    int e  = blockIdx.z;
    int up = blockIdx.x >> 4;
    int bx = blockIdx.x & 15;
    int by = blockIdx.y;

    if (e < NE) {
        int M = d_cnt[e];
        if (by * BM >= M) return;
        const float* B = (up ? Wu : Wg) + (size_t)e * IS * HD;
        float* C = (up ? d_bufU : d_bufG) + (size_t)e * TMAX * IS;
        gemm_core<1, 0>(d_xr, B, C, d_tok + e * TMAX, M, HD, IS, by, bx);
    } else {
        if (by * BM >= Tn) return;
        const float* B = up ? Su : Sg;
        float* C = up ? d_sU : d_sG;
        gemm_core<0, 0>(d_xr, B, C, nullptr, Tn, HD, SIW, by, bx);
    }
}

// ---------------- down GEMMs ----------------
__global__ __launch_bounds__(256, 2)
void gemm_sd(const float* __restrict__ Sd, float* __restrict__ out, int Tn) {
    if ((int)blockIdx.y * BM >= Tn) return;
    gemm_core<0, 0>(d_sG, Sd, out, nullptr, Tn, SIW, HD, blockIdx.y, blockIdx.x);
}

__global__ __launch_bounds__(256, 2)
void gemm_rd(const float* __restrict__ Wd, float* __restrict__ out) {
    int e = blockIdx.z;
    int M = d_cnt[e];
    if ((int)blockIdx.y * BM >= M) return;
    gemm_core<0, 1>(d_bufG + (size_t)e * TMAX * IS,
                    Wd + (size_t)e * HD * IS,
                    out, d_tok + e * TMAX, M, IS, HD, blockIdx.y, blockIdx.x);
}

// ---------------- fused activation (routed z<NE, shared z==NE) ----------------
__device__ __forceinline__ float silu_f(float v) {
    return v / (1.f + expf(-v));
}

__global__ void act_kernel() {
    int e   = blockIdx.y;
    int row = blockIdx.x;
    float w;
    float4 *g4;
    const float4 *u4;
    if (e < NE) {
        if (row >= d_cnt[e]) return;
        w = d_wgt[e * TMAX + row];
        size_t base = ((size_t)e * TMAX + row) * IS;
        g4 = (float4*)(d_bufG + base);
        u4 = (const float4*)(d_bufU + base);
    } else {
        w = 1.f;
        size_t base = (size_t)row * SIW;
        g4 = (float4*)(d_sG + base);
        u4 = (const float4*)(d_sU + base);
    }
    for (int i = threadIdx.x; i < IS / 4; i += blockDim.x) {
        float4 g = g4[i], u = u4[i], z;
        z.x = rndf(silu_f(g.x) * u.x * w);
        z.y = rndf(silu_f(g.y) * u.y * w);
        z.z = rndf(silu_f(g.z) * u.z * w);
        z.w = rndf(silu_f(g.w) * u.w * w);
        g4[i] = z;
    }
}

// ---------------- launch ----------------
extern "C" void kernel_launch(void* const* d_in, const int* in_sizes, int n_in,
                              void* d_out, int out_size) {
    const float* x    = (const float*)d_in[0];
    const float* gw   = (const float*)d_in[1];
    const float* bias = (const float*)d_in[2];
    const float* Wg   = (const float*)d_in[3];
    const float* Wu   = (const float*)d_in[4];
    const float* Wd   = (const float*)d_in[5];
    const float* Sg   = (const float*)d_in[6];
    const float* Su   = (const float*)d_in[7];
    const float* Sd   = (const float*)d_in[8];
    float* out = (float*)d_out;

    int Tn = in_sizes[0] / HD;            // 4096 tokens
    int mt = (Tn + BM - 1) / BM;          // 32

    static int smem_set = 0;
    if (!smem_set) {
        cudaFuncSetAttribute(gemm_gu, cudaFuncAttributeMaxDynamicSharedMemorySize, DSMEM_BYTES);
        cudaFuncSetAttribute(gemm_sd, cudaFuncAttributeMaxDynamicSharedMemorySize, DSMEM_BYTES);
        cudaFuncSetAttribute(gemm_rd, cudaFuncAttributeMaxDynamicSharedMemorySize, DSMEM_BYTES);
        smem_set = 1;
    }

    zero_cnt_kernel<<<1, 32>>>();
    router_kernel<<<Tn, 128>>>(x, gw, bias);
    round_kernel<<<2048, 256>>>((const float4*)x, (int)((size_t)Tn * HD / 4));

    // all four gate/up GEMMs (routed x16 experts + shared) in ONE launch
    gemm_gu<<<dim3(32, 32, NE + 1), 256, DSMEM_BYTES>>>(Wg, Wu, Sg, Su, Tn);

    // fused activation (routed + shared)
    act_kernel<<<dim3(Tn, NE + 1), 256>>>();

    // shared down (plain store) then routed down (atomicAdd) — stream-ordered
    gemm_sd<<<dim3(HD / BN, mt, 1), 256, DSMEM_BYTES>>>(Sd, out, Tn);
    gemm_rd<<<dim3(HD / BN, TMAX / BM, NE), 256, DSMEM_BYTES>>>(Wd, out);

    (void)n_in; (void)out_size;
}